// round 1
// baseline (speedup 1.0000x reference)
#include <cuda_runtime.h>
#include <math_constants.h>

#define Bb   4
#define NQ   4096
#define NP   2048
#define D    256
#define KNN  16
#define PAIR_ROWS (Bb*NQ*KNN)   /* 262144 */

// ---------------- scratch (device globals; no allocation) ----------------
__device__ float g_ck [Bb*NP*D];        // Wg1@Wk folded per-point keys
__device__ float g_v  [Bb*NP*D];        // points @ Wv^T
__device__ float g_b3 [Bb*NP*D];        // Wd1 @ xyz
__device__ float g_aq [Bb*NQ*D];        // Wd1 @ xyz_q + bd1
__device__ int   g_knn[Bb*NQ*KNN];
__device__ float g_h  [PAIR_ROWS*D];    // relu(Aq - B3)
__device__ float g_pos[PAIR_ROWS*D];    // Wd2 h + bd2
__device__ float g_t  [PAIR_ROWS*D];    // relu(cq - ck + Md h + c0)
__device__ float g_at [PAIR_ROWS*D];    // Wg2 t + bg2 (pre-softmax)
__device__ float g_Wcat[2*D*D];         // [Wd2 ; Md=Wg1@Wd2]
__device__ float g_Wkk [D*D];           // Wg1@Wk
__device__ float g_cq[Bb*D];            // Wg1 @ (Wq lat)
__device__ float g_c0[D];               // Wg1@bd2 + bg1
__device__ float g_ag[Bb*D];            // gamma-MLP output for global token
__device__ float g_vg[Bb*D];            // Wvg lat

// ---------------- weight folding ----------------
__global__ void k_fold(const float* __restrict__ Wd2, const float* __restrict__ Wg1,
                       const float* __restrict__ Wk)
{
    int gid = blockIdx.x * 256 + threadIdx.x;
    if (gid < D*D) { g_Wcat[gid] = Wd2[gid]; return; }
    if (gid < 2*D*D) {
        int i = gid - D*D; int f = i >> 8, j = i & 255;
        float acc = 0.f;
        #pragma unroll 8
        for (int c = 0; c < D; c++) acc = fmaf(Wg1[f*D+c], Wd2[c*D+j], acc);
        g_Wcat[D*D + i] = acc; return;
    }
    int i = gid - 2*D*D; if (i >= D*D) return;
    int f = i >> 8, j = i & 255;
    float acc = 0.f;
    #pragma unroll 8
    for (int c = 0; c < D; c++) acc = fmaf(Wg1[f*D+c], Wk[c*D+j], acc);
    g_Wkk[i] = acc;
}

// ---------------- per-batch small vectors ----------------
__device__ __forceinline__ float dot256(const float* __restrict__ w, const float* __restrict__ s)
{
    float acc = 0.f;
    #pragma unroll 8
    for (int c = 0; c < 256; c++) acc = fmaf(w[c], s[c], acc);
    return acc;
}

__global__ void k_small(const float* __restrict__ lat,
                        const float* __restrict__ Wq,  const float* __restrict__ Wkg,
                        const float* __restrict__ Wvg, const float* __restrict__ Wg1,
                        const float* __restrict__ bg1, const float* __restrict__ Wg2,
                        const float* __restrict__ bg2, const float* __restrict__ bd2)
{
    __shared__ float s_in[256], s_qa[256], s_x[256], s_t[256];
    int f = threadIdx.x;
    // c0 = Wg1@bd2 + bg1
    {
        float acc = bg1[f];
        #pragma unroll 8
        for (int c = 0; c < 256; c++) acc = fmaf(Wg1[f*256+c], bd2[c], acc);
        g_c0[f] = acc;
    }
    for (int b = 0; b < Bb; b++) {
        __syncthreads();
        s_in[f] = lat[b*256+f];
        __syncthreads();
        float qa = dot256(Wq  + f*256, s_in);
        float kg = dot256(Wkg + f*256, s_in);
        g_vg[b*256+f] = dot256(Wvg + f*256, s_in);
        __syncthreads();
        s_qa[f] = qa;
        s_x [f] = qa - kg;
        __syncthreads();
        g_cq[b*256+f] = dot256(Wg1 + f*256, s_qa);
        float tg = dot256(Wg1 + f*256, s_x) + bg1[f];
        s_t[f] = fmaxf(tg, 0.f);
        __syncthreads();
        g_ag[b*256+f] = dot256(Wg2 + f*256, s_t) + bg2[f];
    }
}

// ---------------- 3->256 projections of coordinates ----------------
__global__ void k_b3aq(const float* __restrict__ xyz, const float* __restrict__ xyz_q,
                       const float* __restrict__ Wd1, const float* __restrict__ bd1)
{
    int gid = blockIdx.x * 256 + threadIdx.x;
    int row = gid >> 8, f = gid & 255;
    float w0 = Wd1[f*3+0], w1 = Wd1[f*3+1], w2 = Wd1[f*3+2];
    if (row < Bb*NP) {
        const float* p = xyz + row*3;
        g_b3[gid] = fmaf(w0, p[0], fmaf(w1, p[1], w2 * p[2]));
    } else {
        int r = row - Bb*NP; if (r >= Bb*NQ) return;
        const float* p = xyz_q + r*3;
        g_aq[r*256+f] = fmaf(w0, p[0], fmaf(w1, p[1], fmaf(w2, p[2], bd1[f])));
    }
}

// ---------------- KNN: one thread per query, streaming top-16 ----------------
__global__ void k_knn(const float* __restrict__ xyz, const float* __restrict__ xyz_q)
{
    __shared__ float sx[NP], sy[NP], sz[NP], sn2[NP];
    int batch = blockIdx.x >> 4;     // 16 blocks of 256 queries per batch
    int tid = threadIdx.x;
    const float* xb = xyz + batch * NP * 3;
    for (int i = tid; i < NP; i += 256) {
        float x = xb[i*3], y = xb[i*3+1], z = xb[i*3+2];
        sx[i] = x; sy[i] = y; sz[i] = z;
        sn2[i] = x*x + y*y + z*z;
    }
    __syncthreads();
    int qg = blockIdx.x * 256 + tid;             // b*4096 + q
    const float* qp = xyz_q + qg*3;
    float qx = qp[0], qy = qp[1], qz = qp[2];
    float qn2 = qx*qx + qy*qy + qz*qz;

    float dist[KNN]; int idxr[KNN];
    #pragma unroll
    for (int j = 0; j < KNN; j++) { dist[j] = CUDART_INF_F; idxr[j] = 0; }
    float worst = CUDART_INF_F; int ws = 0;

    for (int n = 0; n < NP; n++) {
        // same formula as reference: |q|^2 + |p|^2 - 2 q.p
        float dp = fmaf(qx, sx[n], fmaf(qy, sy[n], qz * sz[n]));
        float d2 = qn2 + sn2[n] - 2.f * dp;
        if (d2 < worst) {
            #pragma unroll
            for (int j = 0; j < KNN; j++) if (j == ws) { dist[j] = d2; idxr[j] = n; }
            worst = dist[0]; ws = 0;
            #pragma unroll
            for (int j = 1; j < KNN; j++) if (dist[j] > worst) { worst = dist[j]; ws = j; }
        }
    }
    int base = qg * KNN;
    #pragma unroll
    for (int j = 0; j < KNN; j++) g_knn[base + j] = idxr[j];
}

// ---------------- h = relu(Aq - B3[knn]) ----------------
__global__ void k_h()
{
    int gid = blockIdx.x * 256 + threadIdx.x;   // float4 index, total 16.7M
    int m  = gid >> 6;                          // pair row (b,q,j)
    int f4 = gid & 63;
    int b  = m >> 16;
    int n  = g_knn[m];
    float4 a = ((const float4*)g_aq)[(m >> 4) * 64 + f4];
    float4 p = ((const float4*)g_b3)[(b*NP + n) * 64 + f4];
    float4 h;
    h.x = fmaxf(a.x - p.x, 0.f);
    h.y = fmaxf(a.y - p.y, 0.f);
    h.z = fmaxf(a.z - p.z, 0.f);
    h.w = fmaxf(a.w - p.w, 0.f);
    ((float4*)g_h)[gid] = h;
}

// ---------------- tiled fp32 GEMM: C = A @ W^T, K=256, fused epilogues ----------------
// mode 0: A=points, W=g_Wkk  -> g_ck
// mode 3: A=points, W=Wv     -> g_v
// mode 1: A=g_h,    W=g_Wcat -> cols<256: g_pos=acc+bd2 ; cols>=256: g_t=relu(acc+cq-ck+c0)
// mode 2: A=g_t,    W=Wg2    -> g_at = acc + bg2
__global__ __launch_bounds__(256) void sgemm(const float* __restrict__ Aarg,
                                             const float* __restrict__ Warg,
                                             int mode, const float* __restrict__ epi_b)
{
    __shared__ float As[16][132];
    __shared__ float Ws[16][132];
    const float* A = (mode == 1) ? g_h : ((mode == 2) ? g_t : Aarg);
    const float* W = (mode == 0) ? g_Wkk : ((mode == 1) ? g_Wcat : Warg);
    const int bm = blockIdx.y << 7;
    const int bn = blockIdx.x << 7;
    const int tid = threadIdx.x;
    const int tx = tid & 15, ty = tid >> 4;

    float acc[8][8];
    #pragma unroll
    for (int i = 0; i < 8; i++)
        #pragma unroll
        for (int j = 0; j < 8; j++) acc[i][j] = 0.f;

    for (int k0 = 0; k0 < 256; k0 += 16) {
        #pragma unroll
        for (int i = 0; i < 2; i++) {
            int l = tid + (i << 8);
            int r = l >> 2, kc = (l & 3) << 2;
            float4 va = *(const float4*)(A + (bm + r) * 256 + k0 + kc);
            As[kc+0][r] = va.x; As[kc+1][r] = va.y; As[kc+2][r] = va.z; As[kc+3][r] = va.w;
            float4 vw = *(const float4*)(W + (bn + r) * 256 + k0 + kc);
            Ws[kc+0][r] = vw.x; Ws[kc+1][r] = vw.y; Ws[kc+2][r] = vw.z; Ws[kc+3][r] = vw.w;
        }
        __syncthreads();
        #pragma unroll
        for (int kk = 0; kk < 16; kk++) {
            float a[8], bb[8];
            *(float4*)(a)      = *(const float4*)&As[kk][ty << 3];
            *(float4*)(a + 4)  = *(const float4*)&As[kk][(ty << 3) + 4];
            *(float4*)(bb)     = *(const float4*)&Ws[kk][tx << 3];
            *(float4*)(bb + 4) = *(const float4*)&Ws[kk][(tx << 3) + 4];
            #pragma unroll
            for (int i = 0; i < 8; i++)
                #pragma unroll
                for (int j = 0; j < 8; j++) acc[i][j] = fmaf(a[i], bb[j], acc[i][j]);
        }
        __syncthreads();
    }

    int c0col = bn + (tx << 3);
    if (mode == 0 || mode == 3) {
        float* dst = (mode == 0) ? g_ck : g_v;
        #pragma unroll
        for (int i = 0; i < 8; i++) {
            int m = bm + (ty << 3) + i;
            *(float4*)(dst + m*256 + c0col)     = make_float4(acc[i][0], acc[i][1], acc[i][2], acc[i][3]);
            *(float4*)(dst + m*256 + c0col + 4) = make_float4(acc[i][4], acc[i][5], acc[i][6], acc[i][7]);
        }
    } else if (mode == 2) {
        float b0[8];
        #pragma unroll
        for (int j = 0; j < 8; j++) b0[j] = epi_b[c0col + j];
        #pragma unroll
        for (int i = 0; i < 8; i++) {
            int m = bm + (ty << 3) + i;
            #pragma unroll
            for (int j = 0; j < 8; j++)
                g_at[m*256 + c0col + j] = acc[i][j] + b0[j];
        }
    } else { // mode 1
        if (bn < 256) {
            float b0[8];
            #pragma unroll
            for (int j = 0; j < 8; j++) b0[j] = epi_b[c0col + j];
            #pragma unroll
            for (int i = 0; i < 8; i++) {
                int m = bm + (ty << 3) + i;
                #pragma unroll
                for (int j = 0; j < 8; j++)
                    g_pos[m*256 + c0col + j] = acc[i][j] + b0[j];
            }
        } else {
            int f0 = c0col - 256;
            float c0v[8];
            #pragma unroll
            for (int j = 0; j < 8; j++) c0v[j] = g_c0[f0 + j];
            #pragma unroll
            for (int i = 0; i < 8; i++) {
                int m = bm + (ty << 3) + i;
                int b = m >> 16;
                int n = g_knn[m];
                const float* ckrow = g_ck + (b*NP + n) * 256;
                const float* cqrow = g_cq + b * 256;
                #pragma unroll
                for (int j = 0; j < 8; j++) {
                    int f = f0 + j;
                    float v = acc[i][j] + cqrow[f] - ckrow[f] + c0v[j];
                    g_t[m*256 + f] = fmaxf(v, 0.f);
                }
            }
        }
    }
}

// ---------------- softmax over 17 neighbors + weighted sum ----------------
__global__ void k_final(float* __restrict__ out)
{
    int bq = blockIdx.x;            // b*4096 + q
    int f  = threadIdx.x;
    int b  = bq >> 12;
    int m0 = bq * KNN;

    float a[KNN];
    float ag = g_ag[b*256 + f];
    float amax = ag;
    #pragma unroll
    for (int j = 0; j < KNN; j++) {
        a[j] = g_at[(m0 + j) * 256 + f];
        amax = fmaxf(amax, a[j]);
    }
    float s = __expf(ag - amax);
    float o = s * g_vg[b*256 + f];
    #pragma unroll
    for (int j = 0; j < KNN; j++) {
        float e = __expf(a[j] - amax);
        s += e;
        int n = g_knn[m0 + j];
        o += e * (g_v[(b*NP + n) * 256 + f] + g_pos[(m0 + j) * 256 + f]);
    }
    out[bq*256 + f] = o / s;
}

// ---------------- launch ----------------
extern "C" void kernel_launch(void* const* d_in, const int* in_sizes, int n_in,
                              void* d_out, int out_size)
{
    const float* xyz_q  = (const float*)d_in[0];
    const float* lat    = (const float*)d_in[1];
    const float* xyz    = (const float*)d_in[2];
    const float* points = (const float*)d_in[3];
    const float* Wd1 = (const float*)d_in[4];  const float* bd1 = (const float*)d_in[5];
    const float* Wd2 = (const float*)d_in[6];  const float* bd2 = (const float*)d_in[7];
    const float* Wg1 = (const float*)d_in[8];  const float* bg1 = (const float*)d_in[9];
    const float* Wg2 = (const float*)d_in[10]; const float* bg2 = (const float*)d_in[11];
    const float* Wkg = (const float*)d_in[12]; const float* Wvg = (const float*)d_in[13];
    const float* Wq  = (const float*)d_in[14]; const float* Wk  = (const float*)d_in[15];
    const float* Wv  = (const float*)d_in[16];
    float* out = (float*)d_out;
    (void)in_sizes; (void)n_in; (void)out_size; (void)Wk;

    k_fold <<<768, 256>>>(Wd2, Wg1, d_in[15] ? (const float*)d_in[15] : Wd2);
    k_small<<<1, 256>>>(lat, Wq, Wkg, Wvg, Wg1, bg1, Wg2, bg2, bd2);
    k_b3aq <<<(Bb*NP + Bb*NQ), 256>>>(xyz, xyz_q, Wd1, bd1);
    k_knn  <<<Bb*NQ/256, 256>>>(xyz, xyz_q);

    // per-point projections: ck = points @ (Wg1 Wk)^T ; v = points @ Wv^T
    sgemm<<<dim3(2, 64), 256>>>(points, nullptr, 0, nullptr);
    sgemm<<<dim3(2, 64), 256>>>(points, Wv,      3, nullptr);

    // pair-level pipeline
    k_h<<<PAIR_ROWS * 64 / 256, 256>>>();
    sgemm<<<dim3(4, PAIR_ROWS/128), 256>>>(nullptr, nullptr, 1, bd2);   // pos + t
    sgemm<<<dim3(2, PAIR_ROWS/128), 256>>>(nullptr, Wg2,     2, bg2);   // attn

    k_final<<<Bb*NQ, 256>>>(out);
}

// round 3
// speedup vs baseline: 2.2248x; 2.2248x over previous
#include <cuda_runtime.h>
#include <cuda_fp16.h>
#include <math_constants.h>
#include <cstdint>

#define Bb   4
#define NQ   4096
#define NP   2048
#define D    256
#define KNN  16
#define PAIR_ROWS (Bb*NQ*KNN)   /* 262144 */

// ================= PTX helpers (baseline ISA only — no tcgen05) =================
__device__ __forceinline__ uint32_t smem_to_u32(const void* p) {
    uint32_t a;
    asm("{ .reg .u64 t; cvta.to.shared.u64 t, %1; cvt.u32.u64 %0, t; }" : "=r"(a) : "l"(p));
    return a;
}
#define CP_ASYNC16(dst, src) \
    asm volatile("cp.async.cg.shared.global [%0], [%1], 16;" :: "r"(dst), "l"(src))
#define CP_COMMIT() asm volatile("cp.async.commit_group;" ::: "memory")
#define CP_WAIT(n)  asm volatile("cp.async.wait_group %0;" :: "n"(n) : "memory")
#define LDSM_X4(r0,r1,r2,r3, addr) \
    asm volatile("ldmatrix.sync.aligned.m8n8.x4.shared.b16 {%0,%1,%2,%3}, [%4];" \
        : "=r"(r0), "=r"(r1), "=r"(r2), "=r"(r3) : "r"(addr))
#define MMA16816(cc, a0,a1,a2,a3, b0,b1) \
    asm volatile("mma.sync.aligned.m16n8k16.row.col.f32.f16.f16.f32 " \
        "{%0,%1,%2,%3}, {%4,%5,%6,%7}, {%8,%9}, {%0,%1,%2,%3};" \
        : "+f"((cc)[0]), "+f"((cc)[1]), "+f"((cc)[2]), "+f"((cc)[3]) \
        : "r"(a0), "r"(a1), "r"(a2), "r"(a3), "r"(b0), "r"(b1))
#define SW128(off) ((off) ^ (((off) >> 3) & 0x70))

// ================= scratch (device globals) =================
__device__ float  g_ck [Bb*NP*D];       // (Wg1@Wk) per-point keys
__device__ float  g_v  [Bb*NP*D];       // points @ Wv^T
__device__ float  g_b3 [Bb*NP*D];       // Wd1 @ xyz
__device__ float  g_aq [Bb*NQ*D];       // Wd1 @ xyz_q + bd1
__device__ int    g_knn[Bb*NQ*KNN];
__device__ __half g_h16[PAIR_ROWS*D];   // relu(Aq - B3)   (GEMM-1 input)
__device__ float  g_pos[PAIR_ROWS*D];   // Wd2 h + bd2     (fp32 for precision)
__device__ __half g_t16[PAIR_ROWS*D];   // relu(Md h + cq - ck + c0) (GEMM-2 input)
__device__ float  g_at [PAIR_ROWS*D];   // Wg2 t + bg2     (fp32 logits)
__device__ float  g_Wcat[2*D*D];        // [Wd2 ; Md=Wg1@Wd2]
__device__ __half g_Wcat16[2*D*D];
__device__ __half g_Wg2_16[D*D];
__device__ float  g_Wkk [D*D];          // Wg1@Wk
__device__ float  g_cq[Bb*D];           // Wg1 @ (Wq lat)
__device__ float  g_c0[D];              // Wg1@bd2 + bg1
__device__ float  g_ag[Bb*D];           // gamma-MLP output for global token
__device__ float  g_vg[Bb*D];           // Wvg lat

// ================= weight folding =================
__global__ void k_fold(const float* __restrict__ Wd2, const float* __restrict__ Wg1,
                       const float* __restrict__ Wk)
{
    int gid = blockIdx.x * 256 + threadIdx.x;
    if (gid < D*D) { g_Wcat[gid] = Wd2[gid]; return; }
    if (gid < 2*D*D) {
        int i = gid - D*D; int f = i >> 8, j = i & 255;
        float acc = 0.f;
        #pragma unroll 8
        for (int c = 0; c < D; c++) acc = fmaf(Wg1[f*D+c], Wd2[c*D+j], acc);
        g_Wcat[D*D + i] = acc; return;
    }
    int i = gid - 2*D*D; if (i >= D*D) return;
    int f = i >> 8, j = i & 255;
    float acc = 0.f;
    #pragma unroll 8
    for (int c = 0; c < D; c++) acc = fmaf(Wg1[f*D+c], Wk[c*D+j], acc);
    g_Wkk[i] = acc;
}

__global__ void k_cvt(const float* __restrict__ Wg2)
{
    int gid = blockIdx.x * 256 + threadIdx.x;
    if (gid < 2*D*D) { g_Wcat16[gid] = __float2half(g_Wcat[gid]); return; }
    int i = gid - 2*D*D; if (i >= D*D) return;
    g_Wg2_16[i] = __float2half(Wg2[i]);
}

// ================= per-batch small vectors =================
__device__ __forceinline__ float dot256(const float* __restrict__ w, const float* __restrict__ s)
{
    float acc = 0.f;
    #pragma unroll 8
    for (int c = 0; c < 256; c++) acc = fmaf(w[c], s[c], acc);
    return acc;
}

__global__ void k_small(const float* __restrict__ lat,
                        const float* __restrict__ Wq,  const float* __restrict__ Wkg,
                        const float* __restrict__ Wvg, const float* __restrict__ Wg1,
                        const float* __restrict__ bg1, const float* __restrict__ Wg2,
                        const float* __restrict__ bg2, const float* __restrict__ bd2)
{
    __shared__ float s_in[256], s_qa[256], s_x[256], s_t[256];
    int f = threadIdx.x;
    {
        float acc = bg1[f];
        #pragma unroll 8
        for (int c = 0; c < 256; c++) acc = fmaf(Wg1[f*256+c], bd2[c], acc);
        g_c0[f] = acc;
    }
    for (int b = 0; b < Bb; b++) {
        __syncthreads();
        s_in[f] = lat[b*256+f];
        __syncthreads();
        float qa = dot256(Wq  + f*256, s_in);
        float kg = dot256(Wkg + f*256, s_in);
        g_vg[b*256+f] = dot256(Wvg + f*256, s_in);
        __syncthreads();
        s_qa[f] = qa;
        s_x [f] = qa - kg;
        __syncthreads();
        g_cq[b*256+f] = dot256(Wg1 + f*256, s_qa);
        float tg = dot256(Wg1 + f*256, s_x) + bg1[f];
        s_t[f] = fmaxf(tg, 0.f);
        __syncthreads();
        g_ag[b*256+f] = dot256(Wg2 + f*256, s_t) + bg2[f];
    }
}

// ================= 3->256 coordinate projections =================
__global__ void k_b3aq(const float* __restrict__ xyz, const float* __restrict__ xyz_q,
                       const float* __restrict__ Wd1, const float* __restrict__ bd1)
{
    int gid = blockIdx.x * 256 + threadIdx.x;
    int row = gid >> 8, f = gid & 255;
    float w0 = Wd1[f*3+0], w1 = Wd1[f*3+1], w2 = Wd1[f*3+2];
    if (row < Bb*NP) {
        const float* p = xyz + row*3;
        g_b3[gid] = fmaf(w0, p[0], fmaf(w1, p[1], w2 * p[2]));
    } else {
        int r = row - Bb*NP; if (r >= Bb*NQ) return;
        const float* p = xyz_q + r*3;
        g_aq[r*256+f] = fmaf(w0, p[0], fmaf(w1, p[1], fmaf(w2, p[2], bd1[f])));
    }
}

// ================= KNN: 4 threads/query, 512 pts each + smem merge =================
__global__ __launch_bounds__(128) void k_knn(const float* __restrict__ xyz,
                                             const float* __restrict__ xyz_q)
{
    __shared__ float sx[NP], sy[NP], sz[NP], sn2[NP];       // 32 KB
    __shared__ float cd[64*32];                              // 8 KB
    __shared__ unsigned short ci[64*32];                     // 4 KB
    int tid = threadIdx.x;
    int qi = tid >> 2, sub = tid & 3;
    int q  = blockIdx.x * 32 + qi;           // b*4096 + q
    int b  = q >> 12;
    const float* xb = xyz + b * NP * 3;
    for (int i = tid; i < NP; i += 128) {
        float x = xb[i*3], y = xb[i*3+1], z = xb[i*3+2];
        sx[i] = x; sy[i] = y; sz[i] = z;
        sn2[i] = x*x + y*y + z*z;
    }
    __syncthreads();
    const float* qp = xyz_q + q*3;
    float qx = qp[0], qy = qp[1], qz = qp[2];
    float qn2 = qx*qx + qy*qy + qz*qz;

    float dist[KNN]; int idxr[KNN];
    #pragma unroll
    for (int j = 0; j < KNN; j++) { dist[j] = CUDART_INF_F; idxr[j] = 0; }
    float worst = CUDART_INF_F; int ws = 0;
    int n0 = sub * 512;
    for (int n = n0; n < n0 + 512; n++) {
        float dp = fmaf(qx, sx[n], fmaf(qy, sy[n], qz * sz[n]));
        float d2 = qn2 + sn2[n] - 2.f * dp;
        if (d2 < worst) {
            #pragma unroll
            for (int j = 0; j < KNN; j++) if (j == ws) { dist[j] = d2; idxr[j] = n; }
            worst = dist[0]; ws = 0;
            #pragma unroll
            for (int j = 1; j < KNN; j++) if (dist[j] > worst) { worst = dist[j]; ws = j; }
        }
    }
    #pragma unroll
    for (int j = 0; j < KNN; j++) {
        int e = sub * KNN + j;
        cd[e*32 + qi] = dist[j];
        ci[e*32 + qi] = (unsigned short)idxr[j];
    }
    __syncthreads();
    if (tid < 32) {
        int qg = blockIdx.x * 32 + tid;
        for (int s = 0; s < KNN; s++) {
            float best = CUDART_INF_F; int be = 0;
            #pragma unroll 8
            for (int e = 0; e < 64; e++) {
                float v = cd[e*32 + tid];
                if (v < best) { best = v; be = e; }
            }
            g_knn[qg*KNN + s] = (int)ci[be*32 + tid];
            cd[be*32 + tid] = CUDART_INF_F;
        }
    }
}

// ================= h = relu(Aq - B3[knn])  (fp16 out) =================
__global__ void k_h16()
{
    int gid = blockIdx.x * 256 + threadIdx.x;
    int m  = gid >> 5;                          // pair row
    int g8 = gid & 31;
    int qrow = m >> 4;
    int b = m >> 16;
    int n = g_knn[m];
    const float4* aq4 = (const float4*)g_aq + (size_t)qrow*64 + g8*2;
    const float4* b34 = (const float4*)g_b3 + ((size_t)(b*NP + n))*64 + g8*2;
    float4 a0 = aq4[0], a1 = aq4[1];
    float4 p0 = b34[0], p1 = b34[1];
    __half2 h0 = __floats2half2_rn(fmaxf(a0.x-p0.x,0.f), fmaxf(a0.y-p0.y,0.f));
    __half2 h1 = __floats2half2_rn(fmaxf(a0.z-p0.z,0.f), fmaxf(a0.w-p0.w,0.f));
    __half2 h2 = __floats2half2_rn(fmaxf(a1.x-p1.x,0.f), fmaxf(a1.y-p1.y,0.f));
    __half2 h3 = __floats2half2_rn(fmaxf(a1.z-p1.z,0.f), fmaxf(a1.w-p1.w,0.f));
    uint4 u;
    u.x = reinterpret_cast<uint32_t&>(h0);
    u.y = reinterpret_cast<uint32_t&>(h1);
    u.z = reinterpret_cast<uint32_t&>(h2);
    u.w = reinterpret_cast<uint32_t&>(h3);
    ((uint4*)g_h16)[gid] = u;
}

// ================= SIMT fp32 GEMM for per-point ck / v (small, 1 GFMA) =================
__global__ __launch_bounds__(256) void sgemm(const float* __restrict__ A,
                                             const float* __restrict__ Wig,
                                             int mode)
{
    __shared__ float As[16][132];
    __shared__ float Ws[16][132];
    const float* W = (mode == 0) ? g_Wkk : Wig;
    const int bm = blockIdx.y << 7;
    const int bn = blockIdx.x << 7;
    const int tid = threadIdx.x;
    const int tx = tid & 15, ty = tid >> 4;

    float acc[8][8];
    #pragma unroll
    for (int i = 0; i < 8; i++)
        #pragma unroll
        for (int j = 0; j < 8; j++) acc[i][j] = 0.f;

    for (int k0 = 0; k0 < 256; k0 += 16) {
        #pragma unroll
        for (int i = 0; i < 2; i++) {
            int l = tid + (i << 8);
            int r = l >> 2, kc = (l & 3) << 2;
            float4 va = *(const float4*)(A + (bm + r) * 256 + k0 + kc);
            As[kc+0][r] = va.x; As[kc+1][r] = va.y; As[kc+2][r] = va.z; As[kc+3][r] = va.w;
            float4 vw = *(const float4*)(W + (bn + r) * 256 + k0 + kc);
            Ws[kc+0][r] = vw.x; Ws[kc+1][r] = vw.y; Ws[kc+2][r] = vw.z; Ws[kc+3][r] = vw.w;
        }
        __syncthreads();
        #pragma unroll
        for (int kk = 0; kk < 16; kk++) {
            float a[8], bb[8];
            *(float4*)(a)      = *(const float4*)&As[kk][ty << 3];
            *(float4*)(a + 4)  = *(const float4*)&As[kk][(ty << 3) + 4];
            *(float4*)(bb)     = *(const float4*)&Ws[kk][tx << 3];
            *(float4*)(bb + 4) = *(const float4*)&Ws[kk][(tx << 3) + 4];
            #pragma unroll
            for (int i = 0; i < 8; i++)
                #pragma unroll
                for (int j = 0; j < 8; j++) acc[i][j] = fmaf(a[i], bb[j], acc[i][j]);
        }
        __syncthreads();
    }
    float* dst = (mode == 0) ? g_ck : g_v;
    int cc = bn + (tx << 3);
    #pragma unroll
    for (int i = 0; i < 8; i++) {
        int m = bm + (ty << 3) + i;
        *(float4*)(dst + m*256 + cc)     = make_float4(acc[i][0], acc[i][1], acc[i][2], acc[i][3]);
        *(float4*)(dst + m*256 + cc + 4) = make_float4(acc[i][4], acc[i][5], acc[i][6], acc[i][7]);
    }
}

// ================= HMMA fp16 GEMM (CTA 128x128, K=256; cp.async pipeline) ========
// mode 1: A=g_h16, B=Wcat16 rows[nbase..nbase+128)
//         ny<2  -> g_pos (fp32) = acc + bd2[slice]
//         ny>=2 -> g_t16 = relu(acc + cq - ck + c0)   [slice cols (ny-2)*128..]
// mode 2: A=g_t16, B=Wg2_16 -> g_at (fp32) = acc + bg2[slice]
__global__ __launch_bounds__(256) void hgemm(int mode, const float* __restrict__ bias)
{
    extern __shared__ __align__(16) char dynsm[];   // 64 KB: [bufA 16K][bufB 16K] x2
    __shared__ float sQC[128];

    const int tid  = threadIdx.x;
    const int lane = tid & 31, wid = tid >> 5;
    const int bm   = blockIdx.x << 7;
    const int ny   = blockIdx.y;
    const int b    = bm >> 16;
    const bool is_t = (mode == 1 && ny >= 2);
    const int nbase = (mode == 1) ? ((ny < 2) ? (ny << 7) : 256 + ((ny - 2) << 7)) : (ny << 7);
    const int ocol0 = is_t ? ((ny - 2) << 7) : ((mode == 1) ? (ny << 7) : (ny << 7));

    const __half* Aop = (mode == 1) ? g_h16 : g_t16;
    const __half* Bop = ((mode == 1) ? g_Wcat16 : g_Wg2_16) + (size_t)nbase * 256;

    if (tid < 128)
        sQC[tid] = is_t ? (g_cq[b*256 + ocol0 + tid] + g_c0[ocol0 + tid])
                        : bias[ocol0 + tid];

    const uint32_t su = smem_to_u32(dynsm);
    const int lrow = tid >> 3;              // 0..31  (row block of 32; x4 iters -> 128 rows)
    const int lseg = tid & 7;               // 16B segment 0..7 within 128B row

    // ---- async load of one K-chunk (64 halves = 128B per row) into buffer bufi
    auto issue_chunk = [&](int kc, int bufi) {
        uint32_t base = su + bufi * 32768;
        const __half* Ap = Aop + (size_t)bm * 256 + (kc << 6) + (lseg << 3);
        const __half* Bp = Bop + (kc << 6) + (lseg << 3);
        #pragma unroll
        for (int i = 0; i < 4; i++) {
            int r = lrow + (i << 5);
            CP_ASYNC16(base + SW128((r << 7) + (lseg << 4)), Ap + (size_t)r * 256);
            CP_ASYNC16(base + 16384 + SW128((r << 7) + (lseg << 4)), Bp + (size_t)r * 256);
        }
    };

    float c[2][8][4];
    #pragma unroll
    for (int mi = 0; mi < 2; mi++)
        #pragma unroll
        for (int ni = 0; ni < 8; ni++)
            #pragma unroll
            for (int k = 0; k < 4; k++) c[mi][ni][k] = 0.f;

    const int warp_m = wid >> 1, warp_n = wid & 1;
    const int lr = lane & 7, sel = lane >> 3;
    const int a_row = warp_m*32 + lr + (sel & 1)*8;     // + mi*16
    const int a_seg = (sel >> 1);                        // + ks*2
    const int b_row = warp_n*64 + lr + (sel >> 1)*8;    // + nj*16
    const int b_seg = (sel & 1);                         // + ks*2

    issue_chunk(0, 0); CP_COMMIT();
    issue_chunk(1, 1); CP_COMMIT();

    #pragma unroll
    for (int kc = 0; kc < 4; kc++) {
        if (kc < 3) { CP_WAIT(1); } else { CP_WAIT(0); }
        __syncthreads();
        uint32_t bufA = su + (kc & 1) * 32768;
        uint32_t bufB = bufA + 16384;
        #pragma unroll
        for (int ks = 0; ks < 4; ks++) {
            uint32_t a[2][4], bf[4][4];
            #pragma unroll
            for (int mi = 0; mi < 2; mi++) {
                uint32_t ad = bufA + SW128(((a_row + mi*16) << 7) + ((a_seg + ks*2) << 4));
                LDSM_X4(a[mi][0], a[mi][1], a[mi][2], a[mi][3], ad);
            }
            #pragma unroll
            for (int nj = 0; nj < 4; nj++) {
                uint32_t bd = bufB + SW128(((b_row + nj*16) << 7) + ((b_seg + ks*2) << 4));
                LDSM_X4(bf[nj][0], bf[nj][1], bf[nj][2], bf[nj][3], bd);
            }
            #pragma unroll
            for (int mi = 0; mi < 2; mi++)
                #pragma unroll
                for (int ni = 0; ni < 8; ni++)
                    MMA16816(c[mi][ni], a[mi][0], a[mi][1], a[mi][2], a[mi][3],
                             bf[ni>>1][(ni&1)*2], bf[ni>>1][(ni&1)*2 + 1]);
        }
        __syncthreads();
        if (kc < 2) { issue_chunk(kc + 2, kc & 1); CP_COMMIT(); }
    }

    // ---- epilogue
    __half* sCK = (__half*)dynsm;           // reuse: 128 rows x stride 136 halves
    if (is_t) {
        #pragma unroll 4
        for (int rr = 0; rr < 16; rr++) {
            int r = wid*16 + rr;
            int n = g_knn[bm + r];
            float4 v = *(const float4*)(g_ck + (((size_t)(b*NP + n)) << 8) + ocol0 + (lane << 2));
            int sa = r*136 + (lane << 2);
            sCK[sa+0] = __float2half(sQC[(lane<<2)+0] - v.x);
            sCK[sa+1] = __float2half(sQC[(lane<<2)+1] - v.y);
            sCK[sa+2] = __float2half(sQC[(lane<<2)+2] - v.z);
            sCK[sa+3] = __float2half(sQC[(lane<<2)+3] - v.w);
        }
        __syncthreads();
    }

    #pragma unroll
    for (int mi = 0; mi < 2; mi++) {
        #pragma unroll
        for (int ni = 0; ni < 8; ni++) {
            int rl = warp_m*32 + mi*16 + (lane >> 2);
            int cl = warp_n*64 + ni*8 + ((lane & 3) << 1);
            if (is_t) {
                __half2 k0 = *(__half2*)&sCK[rl*136 + cl];
                __half2 k1 = *(__half2*)&sCK[(rl+8)*136 + cl];
                float x0 = fmaxf(c[mi][ni][0] + __low2float(k0), 0.f);
                float y0 = fmaxf(c[mi][ni][1] + __high2float(k0), 0.f);
                float x1 = fmaxf(c[mi][ni][2] + __low2float(k1), 0.f);
                float y1 = fmaxf(c[mi][ni][3] + __high2float(k1), 0.f);
                *(__half2*)(g_t16 + (size_t)(bm+rl)  *256 + ocol0 + cl) = __floats2half2_rn(x0, y0);
                *(__half2*)(g_t16 + (size_t)(bm+rl+8)*256 + ocol0 + cl) = __floats2half2_rn(x1, y1);
            } else {
                float bx = sQC[cl], by = sQC[cl+1];
                float* dst = (mode == 1) ? g_pos : g_at;
                *(float2*)(dst + (size_t)(bm+rl)  *256 + ocol0 + cl) =
                    make_float2(c[mi][ni][0] + bx, c[mi][ni][1] + by);
                *(float2*)(dst + (size_t)(bm+rl+8)*256 + ocol0 + cl) =
                    make_float2(c[mi][ni][2] + bx, c[mi][ni][3] + by);
            }
        }
    }
}

// ================= softmax over 17 neighbors + weighted sum =================
__global__ void k_final(float* __restrict__ out)
{
    int bq = blockIdx.x;            // b*4096 + q
    int f  = threadIdx.x;
    int b  = bq >> 12;
    int m0 = bq * KNN;

    float a[KNN];
    float ag = g_ag[b*256 + f];
    float amax = ag;
    #pragma unroll
    for (int j = 0; j < KNN; j++) {
        a[j] = g_at[(size_t)(m0 + j) * 256 + f];
        amax = fmaxf(amax, a[j]);
    }
    float s = __expf(ag - amax);
    float o = s * g_vg[b*256 + f];
    #pragma unroll
    for (int j = 0; j < KNN; j++) {
        float e = __expf(a[j] - amax);
        s += e;
        int n = g_knn[m0 + j];
        o += e * (g_v[(size_t)(b*NP + n) * 256 + f] + g_pos[(size_t)(m0 + j) * 256 + f]);
    }
    out[(size_t)bq*256 + f] = o / s;
}

// ================= launch =================
extern "C" void kernel_launch(void* const* d_in, const int* in_sizes, int n_in,
                              void* d_out, int out_size)
{
    const float* xyz_q  = (const float*)d_in[0];
    const float* lat    = (const float*)d_in[1];
    const float* xyz    = (const float*)d_in[2];
    const float* points = (const float*)d_in[3];
    const float* Wd1 = (const float*)d_in[4];  const float* bd1 = (const float*)d_in[5];
    const float* Wd2 = (const float*)d_in[6];  const float* bd2 = (const float*)d_in[7];
    const float* Wg1 = (const float*)d_in[8];  const float* bg1 = (const float*)d_in[9];
    const float* Wg2 = (const float*)d_in[10]; const float* bg2 = (const float*)d_in[11];
    const float* Wkg = (const float*)d_in[12]; const float* Wvg = (const float*)d_in[13];
    const float* Wq  = (const float*)d_in[14]; const float* Wk  = (const float*)d_in[15];
    const float* Wv  = (const float*)d_in[16];
    float* out = (float*)d_out;
    (void)in_sizes; (void)n_in; (void)out_size;

    const int HG_SMEM = 65536;
    cudaFuncSetAttribute(hgemm, cudaFuncAttributeMaxDynamicSharedMemorySize, HG_SMEM);

    k_fold <<<768, 256>>>(Wd2, Wg1, Wk);
    k_cvt  <<<768, 256>>>(Wg2);
    k_small<<<1, 256>>>(lat, Wq, Wkg, Wvg, Wg1, bg1, Wg2, bg2, bd2);
    k_b3aq <<<(Bb*NP + Bb*NQ), 256>>>(xyz, xyz_q, Wd1, bd1);
    k_knn  <<<Bb*NQ/32, 128>>>(xyz, xyz_q);

    // per-point projections (fp32): ck = points @ (Wg1 Wk)^T ; v = points @ Wv^T
    sgemm<<<dim3(2, 64), 256>>>(points, nullptr, 0);
    sgemm<<<dim3(2, 64), 256>>>(points, Wv,      3);

    // pair-level pipeline (HMMA tensor cores)
    k_h16<<<PAIR_ROWS * 32 / 256, 256>>>();
    hgemm<<<dim3(PAIR_ROWS/128, 4), 256, HG_SMEM>>>(1, bd2);   // pos + t
    hgemm<<<dim3(PAIR_ROWS/128, 2), 256, HG_SMEM>>>(2, bg2);   // attn logits

    k_final<<<Bb*NQ, 256>>>(out);
}

// round 5
// speedup vs baseline: 2.2777x; 1.0238x over previous
#include <cuda_runtime.h>
#include <cuda_fp16.h>
#include <math_constants.h>
#include <cstdint>

#define Bb   4
#define NQ   4096
#define NP   2048
#define D    256
#define KNN  16
#define PAIR_ROWS (Bb*NQ*KNN)   /* 262144 */

// ================= PTX helpers (baseline ISA — no tcgen05) =================
__device__ __forceinline__ uint32_t smem_to_u32(const void* p) {
    uint32_t a;
    asm("{ .reg .u64 t; cvta.to.shared.u64 t, %1; cvt.u32.u64 %0, t; }" : "=r"(a) : "l"(p));
    return a;
}
#define CP_ASYNC16(dst, src) \
    asm volatile("cp.async.cg.shared.global [%0], [%1], 16;" :: "r"(dst), "l"(src))
#define CP_COMMIT() asm volatile("cp.async.commit_group;" ::: "memory")
template<int N> __device__ __forceinline__ void cp_wait() {
    asm volatile("cp.async.wait_group %0;" :: "n"(N) : "memory");
}
__device__ __forceinline__ void cp_wait_dyn(int kc) {   // kc is compile-time after unroll
    if (kc == 0) cp_wait<3>();
    else if (kc == 1) cp_wait<2>();
    else if (kc == 2) cp_wait<1>();
    else cp_wait<0>();
}
#define LDSM_X4(r0,r1,r2,r3, addr) \
    asm volatile("ldmatrix.sync.aligned.m8n8.x4.shared.b16 {%0,%1,%2,%3}, [%4];" \
        : "=r"(r0), "=r"(r1), "=r"(r2), "=r"(r3) : "r"(addr))
#define MMA16816(cc, a0,a1,a2,a3, b0,b1) \
    asm volatile("mma.sync.aligned.m16n8k16.row.col.f32.f16.f16.f32 " \
        "{%0,%1,%2,%3}, {%4,%5,%6,%7}, {%8,%9}, {%0,%1,%2,%3};" \
        : "+f"((cc)[0]), "+f"((cc)[1]), "+f"((cc)[2]), "+f"((cc)[3]) \
        : "r"(a0), "r"(a1), "r"(a2), "r"(a3), "r"(b0), "r"(b1))
#define SW128(off) ((off) ^ (((off) >> 3) & 0x70))

// ================= scratch (device globals) =================
__device__ float  g_ck [Bb*NP*D];       // (Wg1@Wk) per-point keys (fp32, 8MB, L2)
__device__ __half g_v16[Bb*NP*D];       // points @ Wv^T (fp16, 4MB, L2)
__device__ float  g_b3 [Bb*NP*D];       // Wd1 @ xyz (8MB, L2)
__device__ float  g_aq [Bb*NQ*D];       // Wd1 @ xyz_q + bd1 (16MB)
__device__ int    g_knn[Bb*NQ*KNN];
__device__ __half g_pos16[PAIR_ROWS*D]; // Wd2 h + bd2
__device__ __half g_t16 [PAIR_ROWS*D];  // relu(Md h + cq - ck + c0)
__device__ float  g_Wcat[2*D*D];        // [Wd2 ; Md=Wg1@Wd2]
__device__ __half g_Wcat16[2*D*D];
__device__ __half g_Wg2_16[D*D];
__device__ float  g_Wkk [D*D];          // Wg1@Wk
__device__ float  g_cq[Bb*D];           // Wg1 @ (Wq lat)
__device__ float  g_c0[D];              // Wg1@bd2 + bg1
__device__ float  g_ag[Bb*D];           // gamma-MLP output for global token
__device__ float  g_vg[Bb*D];           // Wvg lat

// ================= weight folding =================
__global__ void k_fold(const float* __restrict__ Wd2, const float* __restrict__ Wg1,
                       const float* __restrict__ Wk)
{
    int gid = blockIdx.x * 256 + threadIdx.x;
    if (gid < D*D) { g_Wcat[gid] = Wd2[gid]; return; }
    if (gid < 2*D*D) {
        int i = gid - D*D; int f = i >> 8, j = i & 255;
        float acc = 0.f;
        #pragma unroll 8
        for (int c = 0; c < D; c++) acc = fmaf(Wg1[f*D+c], Wd2[c*D+j], acc);
        g_Wcat[D*D + i] = acc; return;
    }
    int i = gid - 2*D*D; if (i >= D*D) return;
    int f = i >> 8, j = i & 255;
    float acc = 0.f;
    #pragma unroll 8
    for (int c = 0; c < D; c++) acc = fmaf(Wg1[f*D+c], Wk[c*D+j], acc);
    g_Wkk[i] = acc;
}

__global__ void k_cvt(const float* __restrict__ Wg2)
{
    int gid = blockIdx.x * 256 + threadIdx.x;
    if (gid < 2*D*D) { g_Wcat16[gid] = __float2half(g_Wcat[gid]); return; }
    int i = gid - 2*D*D; if (i >= D*D) return;
    g_Wg2_16[i] = __float2half(Wg2[i]);
}

// ================= per-batch small vectors =================
__device__ __forceinline__ float dot256(const float* __restrict__ w, const float* __restrict__ s)
{
    float acc = 0.f;
    #pragma unroll 8
    for (int c = 0; c < 256; c++) acc = fmaf(w[c], s[c], acc);
    return acc;
}

__global__ void k_small(const float* __restrict__ lat,
                        const float* __restrict__ Wq,  const float* __restrict__ Wkg,
                        const float* __restrict__ Wvg, const float* __restrict__ Wg1,
                        const float* __restrict__ bg1, const float* __restrict__ Wg2,
                        const float* __restrict__ bg2, const float* __restrict__ bd2)
{
    __shared__ float s_in[256], s_qa[256], s_x[256], s_t[256];
    int f = threadIdx.x;
    {
        float acc = bg1[f];
        #pragma unroll 8
        for (int c = 0; c < 256; c++) acc = fmaf(Wg1[f*256+c], bd2[c], acc);
        g_c0[f] = acc;
    }
    for (int b = 0; b < Bb; b++) {
        __syncthreads();
        s_in[f] = lat[b*256+f];
        __syncthreads();
        float qa = dot256(Wq  + f*256, s_in);
        float kg = dot256(Wkg + f*256, s_in);
        g_vg[b*256+f] = dot256(Wvg + f*256, s_in);
        __syncthreads();
        s_qa[f] = qa;
        s_x [f] = qa - kg;
        __syncthreads();
        g_cq[b*256+f] = dot256(Wg1 + f*256, s_qa);
        float tg = dot256(Wg1 + f*256, s_x) + bg1[f];
        s_t[f] = fmaxf(tg, 0.f);
        __syncthreads();
        g_ag[b*256+f] = dot256(Wg2 + f*256, s_t) + bg2[f];
    }
}

// ================= 3->256 coordinate projections =================
__global__ void k_b3aq(const float* __restrict__ xyz, const float* __restrict__ xyz_q,
                       const float* __restrict__ Wd1, const float* __restrict__ bd1)
{
    int gid = blockIdx.x * 256 + threadIdx.x;
    int row = gid >> 8, f = gid & 255;
    float w0 = Wd1[f*3+0], w1 = Wd1[f*3+1], w2 = Wd1[f*3+2];
    if (row < Bb*NP) {
        const float* p = xyz + row*3;
        g_b3[gid] = fmaf(w0, p[0], fmaf(w1, p[1], w2 * p[2]));
    } else {
        int r = row - Bb*NP; if (r >= Bb*NQ) return;
        const float* p = xyz_q + r*3;
        g_aq[r*256+f] = fmaf(w0, p[0], fmaf(w1, p[1], fmaf(w2, p[2], bd1[f])));
    }
}

// ================= KNN: 4 threads/query, 512 pts each + smem merge =================
__global__ __launch_bounds__(128) void k_knn(const float* __restrict__ xyz,
                                             const float* __restrict__ xyz_q)
{
    __shared__ float sx[NP], sy[NP], sz[NP], sn2[NP];
    __shared__ float cd[64*32];
    __shared__ unsigned short ci[64*32];
    int tid = threadIdx.x;
    int qi = tid >> 2, sub = tid & 3;
    int q  = blockIdx.x * 32 + qi;
    int b  = q >> 12;
    const float* xb = xyz + b * NP * 3;
    for (int i = tid; i < NP; i += 128) {
        float x = xb[i*3], y = xb[i*3+1], z = xb[i*3+2];
        sx[i] = x; sy[i] = y; sz[i] = z;
        sn2[i] = x*x + y*y + z*z;
    }
    __syncthreads();
    const float* qp = xyz_q + q*3;
    float qx = qp[0], qy = qp[1], qz = qp[2];
    float qn2 = qx*qx + qy*qy + qz*qz;

    float dist[KNN]; int idxr[KNN];
    #pragma unroll
    for (int j = 0; j < KNN; j++) { dist[j] = CUDART_INF_F; idxr[j] = 0; }
    float worst = CUDART_INF_F; int ws = 0;
    int n0 = sub * 512;
    for (int n = n0; n < n0 + 512; n++) {
        float dp = fmaf(qx, sx[n], fmaf(qy, sy[n], qz * sz[n]));
        float d2 = qn2 + sn2[n] - 2.f * dp;
        if (d2 < worst) {
            #pragma unroll
            for (int j = 0; j < KNN; j++) if (j == ws) { dist[j] = d2; idxr[j] = n; }
            worst = dist[0]; ws = 0;
            #pragma unroll
            for (int j = 1; j < KNN; j++) if (dist[j] > worst) { worst = dist[j]; ws = j; }
        }
    }
    #pragma unroll
    for (int j = 0; j < KNN; j++) {
        int e = sub * KNN + j;
        cd[e*32 + qi] = dist[j];
        ci[e*32 + qi] = (unsigned short)idxr[j];
    }
    __syncthreads();
    if (tid < 32) {
        int qg = blockIdx.x * 32 + tid;
        for (int s = 0; s < KNN; s++) {
            float best = CUDART_INF_F; int be = 0;
            #pragma unroll 8
            for (int e = 0; e < 64; e++) {
                float v = cd[e*32 + tid];
                if (v < best) { best = v; be = e; }
            }
            g_knn[qg*KNN + s] = (int)ci[be*32 + tid];
            cd[be*32 + tid] = CUDART_INF_F;
        }
    }
}

// ================= SIMT fp32 GEMM for per-point ck / v =================
__global__ __launch_bounds__(256) void sgemm(const float* __restrict__ A,
                                             const float* __restrict__ Wig,
                                             int mode)
{
    __shared__ float As[16][132];
    __shared__ float Ws[16][132];
    const float* W = (mode == 0) ? g_Wkk : Wig;
    const int bm = blockIdx.y << 7;
    const int bn = blockIdx.x << 7;
    const int tid = threadIdx.x;
    const int tx = tid & 15, ty = tid >> 4;

    float acc[8][8];
    #pragma unroll
    for (int i = 0; i < 8; i++)
        #pragma unroll
        for (int j = 0; j < 8; j++) acc[i][j] = 0.f;

    for (int k0 = 0; k0 < 256; k0 += 16) {
        #pragma unroll
        for (int i = 0; i < 2; i++) {
            int l = tid + (i << 8);
            int r = l >> 2, kc = (l & 3) << 2;
            float4 va = *(const float4*)(A + (bm + r) * 256 + k0 + kc);
            As[kc+0][r] = va.x; As[kc+1][r] = va.y; As[kc+2][r] = va.z; As[kc+3][r] = va.w;
            float4 vw = *(const float4*)(W + (bn + r) * 256 + k0 + kc);
            Ws[kc+0][r] = vw.x; Ws[kc+1][r] = vw.y; Ws[kc+2][r] = vw.z; Ws[kc+3][r] = vw.w;
        }
        __syncthreads();
        #pragma unroll
        for (int kk = 0; kk < 16; kk++) {
            float a[8], bb[8];
            *(float4*)(a)      = *(const float4*)&As[kk][ty << 3];
            *(float4*)(a + 4)  = *(const float4*)&As[kk][(ty << 3) + 4];
            *(float4*)(bb)     = *(const float4*)&Ws[kk][tx << 3];
            *(float4*)(bb + 4) = *(const float4*)&Ws[kk][(tx << 3) + 4];
            #pragma unroll
            for (int i = 0; i < 8; i++)
                #pragma unroll
                for (int j = 0; j < 8; j++) acc[i][j] = fmaf(a[i], bb[j], acc[i][j]);
        }
        __syncthreads();
    }
    int cc = bn + (tx << 3);
    if (mode == 0) {
        #pragma unroll
        for (int i = 0; i < 8; i++) {
            int m = bm + (ty << 3) + i;
            *(float4*)(g_ck + m*256 + cc)     = make_float4(acc[i][0], acc[i][1], acc[i][2], acc[i][3]);
            *(float4*)(g_ck + m*256 + cc + 4) = make_float4(acc[i][4], acc[i][5], acc[i][6], acc[i][7]);
        }
    } else {
        #pragma unroll
        for (int i = 0; i < 8; i++) {
            int m = bm + (ty << 3) + i;
            __half2 h0 = __floats2half2_rn(acc[i][0], acc[i][1]);
            __half2 h1 = __floats2half2_rn(acc[i][2], acc[i][3]);
            __half2 h2 = __floats2half2_rn(acc[i][4], acc[i][5]);
            __half2 h3 = __floats2half2_rn(acc[i][6], acc[i][7]);
            uint4 u;
            u.x = reinterpret_cast<uint32_t&>(h0);
            u.y = reinterpret_cast<uint32_t&>(h1);
            u.z = reinterpret_cast<uint32_t&>(h2);
            u.w = reinterpret_cast<uint32_t&>(h3);
            *(uint4*)(g_v16 + (size_t)m*256 + cc) = u;
        }
    }
}

// ===================================================================
// GEMM-1 (fused h-gen): C[128x256] = h[128x256] @ Wcat[ny]^T
//   ny=0: g_pos16 = acc + bd2
//   ny=1: g_t16   = relu(acc + cq - ck[knn] + c0)
// 512 threads, K=256 fully SMEM-resident (A 64KB regenerated, B 128KB cp.async)
// ===================================================================
__global__ __launch_bounds__(512, 1) void hgemm_pt(const float* __restrict__ bias)
{
    extern __shared__ __align__(16) char dynsm[];   // [A 64KB][B 128KB]
    __shared__ float sQC[256];

    const int tid  = threadIdx.x;
    const int lane = tid & 31, wid = tid >> 5;
    const int bm   = blockIdx.x << 7;
    const int ny   = blockIdx.y;
    const int b    = bm >> 16;

    const __half* Bop = g_Wcat16 + (size_t)(ny << 8) * 256;
    const uint32_t su = smem_to_u32(dynsm);
    const uint32_t sB = su + 65536;
    const int lrow = tid >> 3;              // 0..63
    const int lseg = tid & 7;

    // ---- B: 4 chunk-groups of cp.async (256 rows x 64 halves each)
    #pragma unroll
    for (int c = 0; c < 4; c++) {
        #pragma unroll
        for (int i = 0; i < 4; i++) {
            int r = lrow + (i << 6);
            CP_ASYNC16(sB + c*32768 + SW128((r << 7) + (lseg << 4)),
                       Bop + (size_t)r*256 + (c << 6) + (lseg << 3));
        }
        CP_COMMIT();
    }
    // ---- A: regenerate h = relu(aq - b3[knn]) straight into swizzled SMEM
    #pragma unroll
    for (int c = 0; c < 4; c++) {
        #pragma unroll
        for (int i = 0; i < 2; i++) {
            int idx = tid + (i << 9);
            int r = idx >> 3, sg = idx & 7;
            int m = bm + r;
            int qrow = m >> 4;
            int n = g_knn[m];
            const float4* aq = (const float4*)(g_aq + (size_t)qrow*256 + (c << 6) + (sg << 3));
            const float4* p3 = (const float4*)(g_b3 + (size_t)(b*NP + n)*256 + (c << 6) + (sg << 3));
            float4 a0 = aq[0], a1 = aq[1];
            float4 p0 = p3[0], p1 = p3[1];
            __half2 h0 = __floats2half2_rn(fmaxf(a0.x-p0.x,0.f), fmaxf(a0.y-p0.y,0.f));
            __half2 h1 = __floats2half2_rn(fmaxf(a0.z-p0.z,0.f), fmaxf(a0.w-p0.w,0.f));
            __half2 h2 = __floats2half2_rn(fmaxf(a1.x-p1.x,0.f), fmaxf(a1.y-p1.y,0.f));
            __half2 h3 = __floats2half2_rn(fmaxf(a1.z-p1.z,0.f), fmaxf(a1.w-p1.w,0.f));
            uint4 u;
            u.x = reinterpret_cast<uint32_t&>(h0);
            u.y = reinterpret_cast<uint32_t&>(h1);
            u.z = reinterpret_cast<uint32_t&>(h2);
            u.w = reinterpret_cast<uint32_t&>(h3);
            *(uint4*)(dynsm + c*16384 + SW128((r << 7) + (sg << 4))) = u;
        }
    }
    if (tid < 256)
        sQC[tid] = ny ? (g_cq[b*256 + tid] + g_c0[tid]) : bias[tid];

    float acc[2][8][4];
    #pragma unroll
    for (int mi = 0; mi < 2; mi++)
        #pragma unroll
        for (int ni = 0; ni < 8; ni++)
            #pragma unroll
            for (int k = 0; k < 4; k++) acc[mi][ni][k] = 0.f;

    const int warp_m = wid >> 2, warp_n = wid & 3;
    const int lr = lane & 7, sel = lane >> 3;
    const int a_row = warp_m*32 + lr + (sel & 1)*8;
    const int a_seg = sel >> 1;
    const int b_row = warp_n*64 + lr + (sel >> 1)*8;
    const int b_seg = sel & 1;

    __syncthreads();      // A STS visible CTA-wide

    #pragma unroll
    for (int kc = 0; kc < 4; kc++) {
        cp_wait_dyn(kc);
        __syncthreads();
        uint32_t bufA = su + kc*16384;
        uint32_t bufB = sB + kc*32768;
        #pragma unroll
        for (int ks = 0; ks < 4; ks++) {
            uint32_t a[2][4], bf[4][4];
            #pragma unroll
            for (int mi = 0; mi < 2; mi++) {
                uint32_t ad = bufA + SW128(((a_row + mi*16) << 7) + ((a_seg + ks*2) << 4));
                LDSM_X4(a[mi][0], a[mi][1], a[mi][2], a[mi][3], ad);
            }
            #pragma unroll
            for (int nj = 0; nj < 4; nj++) {
                uint32_t bd = bufB + SW128(((b_row + nj*16) << 7) + ((b_seg + ks*2) << 4));
                LDSM_X4(bf[nj][0], bf[nj][1], bf[nj][2], bf[nj][3], bd);
            }
            #pragma unroll
            for (int mi = 0; mi < 2; mi++)
                #pragma unroll
                for (int ni = 0; ni < 8; ni++)
                    MMA16816(acc[mi][ni], a[mi][0], a[mi][1], a[mi][2], a[mi][3],
                             bf[ni>>1][(ni&1)*2], bf[ni>>1][(ni&1)*2 + 1]);
        }
    }

    // ---- epilogue
    if (ny == 0) {
        #pragma unroll
        for (int mi = 0; mi < 2; mi++)
            #pragma unroll
            for (int ni = 0; ni < 8; ni++) {
                int rl = warp_m*32 + mi*16 + (lane >> 2);
                int cl = warp_n*64 + ni*8 + ((lane & 3) << 1);
                float bx = sQC[cl], by = sQC[cl+1];
                *(__half2*)(g_pos16 + (size_t)(bm+rl)  *256 + cl) =
                    __floats2half2_rn(acc[mi][ni][0] + bx, acc[mi][ni][1] + by);
                *(__half2*)(g_pos16 + (size_t)(bm+rl+8)*256 + cl) =
                    __floats2half2_rn(acc[mi][ni][2] + bx, acc[mi][ni][3] + by);
            }
    } else {
        __syncthreads();                 // reuse smem for staged (sQC - ck)
        __half* sCK = (__half*)dynsm;    // 128 rows x stride 264 halves
        {
            int r = tid >> 2, sub = tid & 3;
            int n = g_knn[bm + r];
            const float4* ck4 = (const float4*)(g_ck + ((size_t)(b*NP + n) << 8) + (sub << 6));
            #pragma unroll
            for (int i = 0; i < 16; i++) {
                float4 v = ck4[i];
                int c0 = (sub << 6) + (i << 2);
                __half2 x0 = __floats2half2_rn(sQC[c0+0] - v.x, sQC[c0+1] - v.y);
                __half2 x1 = __floats2half2_rn(sQC[c0+2] - v.z, sQC[c0+3] - v.w);
                *(__half2*)&sCK[r*264 + c0]     = x0;
                *(__half2*)&sCK[r*264 + c0 + 2] = x1;
            }
        }
        __syncthreads();
        #pragma unroll
        for (int mi = 0; mi < 2; mi++)
            #pragma unroll
            for (int ni = 0; ni < 8; ni++) {
                int rl = warp_m*32 + mi*16 + (lane >> 2);
                int cl = warp_n*64 + ni*8 + ((lane & 3) << 1);
                __half2 k0 = *(__half2*)&sCK[rl*264 + cl];
                __half2 k1 = *(__half2*)&sCK[(rl+8)*264 + cl];
                float x0 = fmaxf(acc[mi][ni][0] + __low2float(k0), 0.f);
                float y0 = fmaxf(acc[mi][ni][1] + __high2float(k0), 0.f);
                float x1 = fmaxf(acc[mi][ni][2] + __low2float(k1), 0.f);
                float y1 = fmaxf(acc[mi][ni][3] + __high2float(k1), 0.f);
                *(__half2*)(g_t16 + (size_t)(bm+rl)  *256 + cl) = __floats2half2_rn(x0, y0);
                *(__half2*)(g_t16 + (size_t)(bm+rl+8)*256 + cl) = __floats2half2_rn(x1, y1);
            }
    }
}

// ===================================================================
// GEMM-2 + fused softmax + output: logits = t @ Wg2^T + bg2, then
// per (query, feature): softmax over 16 neighbors + global token,
// out = sum(e * (v[knn] + pos)) / sum(e)   — written directly.
// ===================================================================
__global__ __launch_bounds__(512, 1) void hgemm_fin(const float* __restrict__ bg2,
                                                    float* __restrict__ out)
{
    extern __shared__ __align__(16) char dynsm[];   // [A 64KB][B 128KB]
    const int tid  = threadIdx.x;
    const int lane = tid & 31, wid = tid >> 5;
    const int bm   = blockIdx.x << 7;
    const int b    = bm >> 16;

    const uint32_t su = smem_to_u32(dynsm);
    const uint32_t sB = su + 65536;
    const int lrow = tid >> 3, lseg = tid & 7;

    #pragma unroll
    for (int c = 0; c < 4; c++) {
        #pragma unroll
        for (int i = 0; i < 2; i++) {       // A: g_t16 tile 128x64
            int idx = tid + (i << 9);
            int r = idx >> 3, sg = idx & 7;
            CP_ASYNC16(su + c*16384 + SW128((r << 7) + (sg << 4)),
                       g_t16 + (size_t)(bm + r)*256 + (c << 6) + (sg << 3));
        }
        #pragma unroll
        for (int i = 0; i < 4; i++) {       // B: Wg2 256x64
            int r = lrow + (i << 6);
            CP_ASYNC16(sB + c*32768 + SW128((r << 7) + (lseg << 4)),
                       g_Wg2_16 + (size_t)r*256 + (c << 6) + (lseg << 3));
        }
        CP_COMMIT();
    }

    float acc[2][8][4];
    #pragma unroll
    for (int mi = 0; mi < 2; mi++)
        #pragma unroll
        for (int ni = 0; ni < 8; ni++)
            #pragma unroll
            for (int k = 0; k < 4; k++) acc[mi][ni][k] = 0.f;

    const int warp_m = wid >> 2, warp_n = wid & 3;
    const int lr = lane & 7, sel = lane >> 3;
    const int a_row = warp_m*32 + lr + (sel & 1)*8;
    const int a_seg = sel >> 1;
    const int b_row = warp_n*64 + lr + (sel >> 1)*8;
    const int b_seg = sel & 1;

    #pragma unroll
    for (int kc = 0; kc < 4; kc++) {
        cp_wait_dyn(kc);
        __syncthreads();
        uint32_t bufA = su + kc*16384;
        uint32_t bufB = sB + kc*32768;
        #pragma unroll
        for (int ks = 0; ks < 4; ks++) {
            uint32_t a[2][4], bf[4][4];
            #pragma unroll
            for (int mi = 0; mi < 2; mi++) {
                uint32_t ad = bufA + SW128(((a_row + mi*16) << 7) + ((a_seg + ks*2) << 4));
                LDSM_X4(a[mi][0], a[mi][1], a[mi][2], a[mi][3], ad);
            }
            #pragma unroll
            for (int nj = 0; nj < 4; nj++) {
                uint32_t bd = bufB + SW128(((b_row + nj*16) << 7) + ((b_seg + ks*2) << 4));
                LDSM_X4(bf[nj][0], bf[nj][1], bf[nj][2], bf[nj][3], bd);
            }
            #pragma unroll
            for (int mi = 0; mi < 2; mi++)
                #pragma unroll
                for (int ni = 0; ni < 8; ni++)
                    MMA16816(acc[mi][ni], a[mi][0], a[mi][1], a[mi][2], a[mi][3],
                             bf[ni>>1][(ni&1)*2], bf[ni>>1][(ni&1)*2 + 1]);
        }
    }

    // ---- fused softmax + weighted-sum epilogue
    // thread holds neighbors j0 = lane>>2 and j1 = j0+8 of query
    // q = (bm + warp_m*32 + mi*16) >> 4, for columns cl, cl+1.
    #pragma unroll
    for (int mi = 0; mi < 2; mi++) {
        int rl0 = warp_m*32 + mi*16 + (lane >> 2);
        int m0r = bm + rl0;
        int m1r = m0r + 8;
        int n0 = g_knn[m0r], n1 = g_knn[m1r];
        int q  = (bm + warp_m*32 + mi*16) >> 4;
        #pragma unroll
        for (int ni = 0; ni < 8; ni++) {
            int cl = warp_n*64 + ni*8 + ((lane & 3) << 1);
            float l00 = acc[mi][ni][0] + bg2[cl];
            float l01 = acc[mi][ni][1] + bg2[cl+1];
            float l10 = acc[mi][ni][2] + bg2[cl];
            float l11 = acc[mi][ni][3] + bg2[cl+1];
            float ag0 = g_ag[b*256 + cl], ag1 = g_ag[b*256 + cl + 1];

            float m0 = fmaxf(l00, l10), m1 = fmaxf(l01, l11);
            #pragma unroll
            for (int msk = 4; msk <= 16; msk <<= 1) {
                m0 = fmaxf(m0, __shfl_xor_sync(0xFFFFFFFFu, m0, msk));
                m1 = fmaxf(m1, __shfl_xor_sync(0xFFFFFFFFu, m1, msk));
            }
            m0 = fmaxf(m0, ag0); m1 = fmaxf(m1, ag1);

            __half2 p0 = *(const __half2*)(g_pos16 + (size_t)m0r*256 + cl);
            __half2 p1 = *(const __half2*)(g_pos16 + (size_t)m1r*256 + cl);
            __half2 v0 = *(const __half2*)(g_v16 + ((size_t)(b*NP + n0))*256 + cl);
            __half2 v1 = *(const __half2*)(g_v16 + ((size_t)(b*NP + n1))*256 + cl);

            float e00 = __expf(l00 - m0), e10 = __expf(l10 - m0);
            float e01 = __expf(l01 - m1), e11 = __expf(l11 - m1);
            float s0 = e00 + e10, s1 = e01 + e11;
            float o0 = e00 * (__low2float(v0)  + __low2float(p0))
                     + e10 * (__low2float(v1)  + __low2float(p1));
            float o1 = e01 * (__high2float(v0) + __high2float(p0))
                     + e11 * (__high2float(v1) + __high2float(p1));
            #pragma unroll
            for (int msk = 4; msk <= 16; msk <<= 1) {
                s0 += __shfl_xor_sync(0xFFFFFFFFu, s0, msk);
                s1 += __shfl_xor_sync(0xFFFFFFFFu, s1, msk);
                o0 += __shfl_xor_sync(0xFFFFFFFFu, o0, msk);
                o1 += __shfl_xor_sync(0xFFFFFFFFu, o1, msk);
            }
            if ((lane >> 2) == 0) {
                float eg0 = __expf(ag0 - m0), eg1 = __expf(ag1 - m1);
                s0 += eg0; s1 += eg1;
                o0 += eg0 * g_vg[b*256 + cl];
                o1 += eg1 * g_vg[b*256 + cl + 1];
                *(float2*)(out + (size_t)q*256 + cl) = make_float2(o0 / s0, o1 / s1);
            }
        }
    }
}

// ================= launch =================
extern "C" void kernel_launch(void* const* d_in, const int* in_sizes, int n_in,
                              void* d_out, int out_size)
{
    const float* xyz_q  = (const float*)d_in[0];
    const float* lat    = (const float*)d_in[1];
    const float* xyz    = (const float*)d_in[2];
    const float* points = (const float*)d_in[3];
    const float* Wd1 = (const float*)d_in[4];  const float* bd1 = (const float*)d_in[5];
    const float* Wd2 = (const float*)d_in[6];  const float* bd2 = (const float*)d_in[7];
    const float* Wg1 = (const float*)d_in[8];  const float* bg1 = (const float*)d_in[9];
    const float* Wg2 = (const float*)d_in[10]; const float* bg2 = (const float*)d_in[11];
    const float* Wkg = (const float*)d_in[12]; const float* Wvg = (const float*)d_in[13];
    const float* Wq  = (const float*)d_in[14]; const float* Wk  = (const float*)d_in[15];
    const float* Wv  = (const float*)d_in[16];
    float* out = (float*)d_out;
    (void)in_sizes; (void)n_in; (void)out_size;

    const int BIG_SMEM = 196608;   // 64KB A + 128KB B
    cudaFuncSetAttribute(hgemm_pt,  cudaFuncAttributeMaxDynamicSharedMemorySize, BIG_SMEM);
    cudaFuncSetAttribute(hgemm_fin, cudaFuncAttributeMaxDynamicSharedMemorySize, BIG_SMEM);

    k_fold <<<768, 256>>>(Wd2, Wg1, Wk);
    k_cvt  <<<768, 256>>>(Wg2);
    k_small<<<1, 256>>>(lat, Wq, Wkg, Wvg, Wg1, bg1, Wg2, bg2, bd2);
    k_b3aq <<<(Bb*NP + Bb*NQ), 256>>>(xyz, xyz_q, Wd1, bd1);
    k_knn  <<<Bb*NQ/32, 128>>>(xyz, xyz_q);

    sgemm<<<dim3(2, 64), 256>>>(points, nullptr, 0);   // ck
    sgemm<<<dim3(2, 64), 256>>>(points, Wv,      1);   // v (fp16)

    hgemm_pt <<<dim3(PAIR_ROWS/128, 2), 512, BIG_SMEM>>>(bd2);
    hgemm_fin<<<PAIR_ROWS/128, 512, BIG_SMEM>>>(bg2, out);
}